// round 2
// baseline (speedup 1.0000x reference)
#include <cuda_runtime.h>
#include <math.h>

// Problem constants
#define BB   4
#define SS   2048
#define DIN  1024
#define NH   16
#define EE   64
#define HS   (NH*EE)   // 1024

// Scratch for projected q,k,v in [b,h,s,e] layout (32 MB each)
__device__ float g_q[BB*NH*SS*EE];
__device__ float g_k[BB*NH*SS*EE];
__device__ float g_v[BB*NH*SS*EE];

// ---------------------------------------------------------------------------
// QKV projection: y[m][n] = sum_d x[m][d] * W[n][d]
//   M = BB*SS = 8192, N = NH*EE = 1024 (per weight matrix), K = DIN = 1024
//   BM=128, BN=64, BK=16, 256 threads, 8x4 microtile
//   blockIdx.z selects q/k/v. Output written as [b,h,s,e].
// ---------------------------------------------------------------------------
__global__ __launch_bounds__(256)
void qkv_gemm(const float* __restrict__ x,
              const float* __restrict__ Wq,
              const float* __restrict__ Wk,
              const float* __restrict__ Wv)
{
    __shared__ float As[16][128];   // k-major
    __shared__ float Bs[16][64];    // k-major

    const float* W   = (blockIdx.z == 0) ? Wq : (blockIdx.z == 1) ? Wk : Wv;
    float*       out = (blockIdx.z == 0) ? g_q : (blockIdx.z == 1) ? g_k : g_v;

    const int m0 = blockIdx.x * 128;
    const int n0 = blockIdx.y * 64;
    const int t  = threadIdx.x;
    const int tm = t >> 4;          // 0..15 -> rows tm*8
    const int tn = t & 15;          // 0..15 -> cols tn*4

    // load-index helpers: 4-float4-per-row chunks
    const int lr = t >> 2;          // 0..63
    const int lc = t & 3;           // 0..3

    float acc[8][4];
#pragma unroll
    for (int i = 0; i < 8; i++)
#pragma unroll
        for (int j = 0; j < 4; j++) acc[i][j] = 0.0f;

    for (int k0 = 0; k0 < DIN; k0 += 16) {
        // --- load A tile: 128 rows x 16 k  (2 float4 per thread) ---
        float4 a0 = *(const float4*)&x[(size_t)(m0 + lr) * DIN + k0 + lc * 4];
        float4 a1 = *(const float4*)&x[(size_t)(m0 + lr + 64) * DIN + k0 + lc * 4];
        // --- load B tile: 64 rows x 16 k  (1 float4 per thread) ---
        float4 b0 = *(const float4*)&W[(size_t)(n0 + lr) * DIN + k0 + lc * 4];

        As[lc*4+0][lr]      = a0.x;
        As[lc*4+1][lr]      = a0.y;
        As[lc*4+2][lr]      = a0.z;
        As[lc*4+3][lr]      = a0.w;
        As[lc*4+0][lr+64]   = a1.x;
        As[lc*4+1][lr+64]   = a1.y;
        As[lc*4+2][lr+64]   = a1.z;
        As[lc*4+3][lr+64]   = a1.w;
        Bs[lc*4+0][lr]      = b0.x;
        Bs[lc*4+1][lr]      = b0.y;
        Bs[lc*4+2][lr]      = b0.z;
        Bs[lc*4+3][lr]      = b0.w;
        __syncthreads();

#pragma unroll
        for (int kk = 0; kk < 16; kk++) {
            float4 alo = *(const float4*)&As[kk][tm*8];
            float4 ahi = *(const float4*)&As[kk][tm*8 + 4];
            float4 bb  = *(const float4*)&Bs[kk][tn*4];
            float av[8] = {alo.x, alo.y, alo.z, alo.w, ahi.x, ahi.y, ahi.z, ahi.w};
            float bv[4] = {bb.x, bb.y, bb.z, bb.w};
#pragma unroll
            for (int i = 0; i < 8; i++)
#pragma unroll
                for (int j = 0; j < 4; j++)
                    acc[i][j] = fmaf(av[i], bv[j], acc[i][j]);
        }
        __syncthreads();
    }

    // epilogue: write to [b,h,s,e]; BN=64 == one head, so h = n0/64, e = tn*4..+3
    const int h = n0 >> 6;
#pragma unroll
    for (int i = 0; i < 8; i++) {
        int m = m0 + tm * 8 + i;
        int b = m / SS;
        int s = m % SS;
        float4 v = make_float4(acc[i][0], acc[i][1], acc[i][2], acc[i][3]);
        *(float4*)&out[(((size_t)(b * NH + h)) * SS + s) * EE + tn * 4] = v;
    }
}

// ---------------------------------------------------------------------------
// Flash attention over one (b,h, 64-row q tile).
//   grid: (SS/64, BB*NH), 256 threads, 4x4 microtile on 64x64 tiles.
//   Dynamic smem: Qs_t[64][64] + Ks_t[64][64] + Vs[64][64] + Ps[64][65]
// ---------------------------------------------------------------------------
#define ATTN_SMEM_FLOATS (3*64*64 + 64*65)
#define ATTN_SMEM_BYTES  (ATTN_SMEM_FLOATS * 4)

__global__ __launch_bounds__(256)
void attn_kernel(float* __restrict__ out)
{
    extern __shared__ float sm[];
    float* Qs = sm;                 // [e][i]  stride 64
    float* Ks = sm + 64*64;         // [e][j]  stride 64
    float* Vs = sm + 2*64*64;       // [j][e]  stride 64
    float* Ps = sm + 3*64*64;       // [i][j]  stride 65 (conflict-free PV reads)

    const int bh = blockIdx.y;
    const int q0 = blockIdx.x * 64;
    const float* Q = g_q + (size_t)bh * SS * EE;
    const float* K = g_k + (size_t)bh * SS * EE;
    const float* V = g_v + (size_t)bh * SS * EE;

    const int t  = threadIdx.x;
    const int tm = t >> 4;          // 0..15 -> q rows tm*4
    const int tn = t & 15;          // 0..15 -> cols tn*4

    // load Q tile transposed: 64 rows x 64 e = 1024 float4, 4 per thread
#pragma unroll
    for (int i = 0; i < 4; i++) {
        int f = i * 256 + t;
        int r = f >> 4;             // 0..63
        int c = f & 15;             // 0..15
        float4 v = *(const float4*)&Q[(size_t)(q0 + r) * EE + c * 4];
        Qs[(c*4+0)*64 + r] = v.x;
        Qs[(c*4+1)*64 + r] = v.y;
        Qs[(c*4+2)*64 + r] = v.z;
        Qs[(c*4+3)*64 + r] = v.w;
    }

    float m_r[4], l_r[4], o[4][4];
#pragma unroll
    for (int i = 0; i < 4; i++) {
        m_r[i] = -1e30f;
        l_r[i] = 0.0f;
#pragma unroll
        for (int j = 0; j < 4; j++) o[i][j] = 0.0f;
    }

    for (int kv0 = 0; kv0 < SS; kv0 += 64) {
        __syncthreads();   // protect Ks/Vs/Ps from previous iteration

        // load K (transposed) and V tiles
#pragma unroll
        for (int i = 0; i < 4; i++) {
            int f = i * 256 + t;
            int r = f >> 4;
            int c = f & 15;
            float4 kv = *(const float4*)&K[(size_t)(kv0 + r) * EE + c * 4];
            Ks[(c*4+0)*64 + r] = kv.x;
            Ks[(c*4+1)*64 + r] = kv.y;
            Ks[(c*4+2)*64 + r] = kv.z;
            Ks[(c*4+3)*64 + r] = kv.w;
            float4 vv = *(const float4*)&V[(size_t)(kv0 + r) * EE + c * 4];
            *(float4*)&Vs[r*64 + c*4] = vv;
        }
        __syncthreads();

        // ---- S = Q K^T * 1/sqrt(E) ----
        float s[4][4];
#pragma unroll
        for (int i = 0; i < 4; i++)
#pragma unroll
            for (int j = 0; j < 4; j++) s[i][j] = 0.0f;

#pragma unroll 8
        for (int e = 0; e < 64; e++) {
            float4 q = *(const float4*)&Qs[e*64 + tm*4];
            float4 k = *(const float4*)&Ks[e*64 + tn*4];
            float qv[4] = {q.x, q.y, q.z, q.w};
            float kv[4] = {k.x, k.y, k.z, k.w};
#pragma unroll
            for (int i = 0; i < 4; i++)
#pragma unroll
                for (int j = 0; j < 4; j++)
                    s[i][j] = fmaf(qv[i], kv[j], s[i][j]);
        }

        // ---- online softmax update (rows owned by tm; reduce across 16 tn lanes) ----
#pragma unroll
        for (int i = 0; i < 4; i++) {
            float tmax = s[i][0];
#pragma unroll
            for (int j = 1; j < 4; j++) tmax = fmaxf(tmax, s[i][j]);
            tmax *= 0.125f;
#pragma unroll
            for (int d = 8; d >= 1; d >>= 1)
                tmax = fmaxf(tmax, __shfl_xor_sync(0xffffffffu, tmax, d));

            float m_new = fmaxf(m_r[i], tmax);
            float alpha = __expf(m_r[i] - m_new);

            float rsum = 0.0f;
            float p[4];
#pragma unroll
            for (int j = 0; j < 4; j++) {
                p[j] = __expf(s[i][j] * 0.125f - m_new);
                rsum += p[j];
            }
#pragma unroll
            for (int d = 8; d >= 1; d >>= 1)
                rsum += __shfl_xor_sync(0xffffffffu, rsum, d);

            l_r[i] = l_r[i] * alpha + rsum;
            m_r[i] = m_new;
#pragma unroll
            for (int j = 0; j < 4; j++) {
                o[i][j] *= alpha;
                Ps[(tm*4 + i)*65 + tn*4 + j] = p[j];
            }
        }
        __syncthreads();

        // ---- O += P V ----
#pragma unroll 4
        for (int j = 0; j < 64; j++) {
            float4 v = *(const float4*)&Vs[j*64 + tn*4];
            float p0 = Ps[(tm*4+0)*65 + j];
            float p1 = Ps[(tm*4+1)*65 + j];
            float p2 = Ps[(tm*4+2)*65 + j];
            float p3 = Ps[(tm*4+3)*65 + j];
            o[0][0] = fmaf(p0, v.x, o[0][0]); o[0][1] = fmaf(p0, v.y, o[0][1]);
            o[0][2] = fmaf(p0, v.z, o[0][2]); o[0][3] = fmaf(p0, v.w, o[0][3]);
            o[1][0] = fmaf(p1, v.x, o[1][0]); o[1][1] = fmaf(p1, v.y, o[1][1]);
            o[1][2] = fmaf(p1, v.z, o[1][2]); o[1][3] = fmaf(p1, v.w, o[1][3]);
            o[2][0] = fmaf(p2, v.x, o[2][0]); o[2][1] = fmaf(p2, v.y, o[2][1]);
            o[2][2] = fmaf(p2, v.z, o[2][2]); o[2][3] = fmaf(p2, v.w, o[2][3]);
            o[3][0] = fmaf(p3, v.x, o[3][0]); o[3][1] = fmaf(p3, v.y, o[3][1]);
            o[3][2] = fmaf(p3, v.z, o[3][2]); o[3][3] = fmaf(p3, v.w, o[3][3]);
        }
    }

    // ---- epilogue: out[b][s][h*64+e] = O / l ----
    const int b = bh / NH;
    const int h = bh % NH;
#pragma unroll
    for (int i = 0; i < 4; i++) {
        float inv_l = 1.0f / l_r[i];
        int sidx = q0 + tm*4 + i;
        float4 v = make_float4(o[i][0]*inv_l, o[i][1]*inv_l, o[i][2]*inv_l, o[i][3]*inv_l);
        *(float4*)&out[((size_t)(b * SS + sidx)) * HS + h * EE + tn * 4] = v;
    }
}

// ---------------------------------------------------------------------------
extern "C" void kernel_launch(void* const* d_in, const int* in_sizes, int n_in,
                              void* d_out, int out_size)
{
    const float* x  = (const float*)d_in[0];
    const float* Wq = (const float*)d_in[1];
    const float* Wk = (const float*)d_in[2];
    const float* Wv = (const float*)d_in[3];
    float* out = (float*)d_out;

    cudaFuncSetAttribute(attn_kernel,
                         cudaFuncAttributeMaxDynamicSharedMemorySize,
                         ATTN_SMEM_BYTES);

    dim3 ggrid(BB * SS / 128, HS / 64, 3);
    qkv_gemm<<<ggrid, 256>>>(x, Wq, Wk, Wv);

    dim3 agrid(SS / 64, BB * NH);
    attn_kernel<<<agrid, 256, ATTN_SMEM_BYTES>>>(out);
}

// round 3
// speedup vs baseline: 1.0003x; 1.0003x over previous
#include <cuda_runtime.h>
#include <math.h>

// Problem constants
#define BB   4
#define SS   2048
#define DIN  1024
#define NH   16
#define EE   64
#define HS   (NH*EE)   // 1024

// Scratch for projected q,k,v in [b,h,s,e] layout (32 MB each)
__device__ float g_q[BB*NH*SS*EE];
__device__ float g_k[BB*NH*SS*EE];
__device__ float g_v[BB*NH*SS*EE];

// ---------------------------------------------------------------------------
// QKV projection: y[m][n] = sum_d x[m][d] * W[n][d]
//   M = BB*SS = 8192, N = NH*EE = 1024 (per weight matrix), K = DIN = 1024
//   BM=128, BN=64, BK=16, 256 threads, 8x4 microtile
//   blockIdx.z selects q/k/v. Output written as [b,h,s,e].
// ---------------------------------------------------------------------------
__global__ __launch_bounds__(256)
void qkv_gemm(const float* __restrict__ x,
              const float* __restrict__ Wq,
              const float* __restrict__ Wk,
              const float* __restrict__ Wv)
{
    __shared__ float As[16][128];   // k-major
    __shared__ float Bs[16][64];    // k-major

    const float* W   = (blockIdx.z == 0) ? Wq : (blockIdx.z == 1) ? Wk : Wv;
    float*       out = (blockIdx.z == 0) ? g_q : (blockIdx.z == 1) ? g_k : g_v;

    const int m0 = blockIdx.x * 128;
    const int n0 = blockIdx.y * 64;
    const int t  = threadIdx.x;
    const int tm = t >> 4;          // 0..15 -> rows tm*8
    const int tn = t & 15;          // 0..15 -> cols tn*4

    // load-index helpers: 4-float4-per-row chunks
    const int lr = t >> 2;          // 0..63
    const int lc = t & 3;           // 0..3

    float acc[8][4];
#pragma unroll
    for (int i = 0; i < 8; i++)
#pragma unroll
        for (int j = 0; j < 4; j++) acc[i][j] = 0.0f;

    for (int k0 = 0; k0 < DIN; k0 += 16) {
        // --- load A tile: 128 rows x 16 k  (2 float4 per thread) ---
        float4 a0 = *(const float4*)&x[(size_t)(m0 + lr) * DIN + k0 + lc * 4];
        float4 a1 = *(const float4*)&x[(size_t)(m0 + lr + 64) * DIN + k0 + lc * 4];
        // --- load B tile: 64 rows x 16 k  (1 float4 per thread) ---
        float4 b0 = *(const float4*)&W[(size_t)(n0 + lr) * DIN + k0 + lc * 4];

        As[lc*4+0][lr]      = a0.x;
        As[lc*4+1][lr]      = a0.y;
        As[lc*4+2][lr]      = a0.z;
        As[lc*4+3][lr]      = a0.w;
        As[lc*4+0][lr+64]   = a1.x;
        As[lc*4+1][lr+64]   = a1.y;
        As[lc*4+2][lr+64]   = a1.z;
        As[lc*4+3][lr+64]   = a1.w;
        Bs[lc*4+0][lr]      = b0.x;
        Bs[lc*4+1][lr]      = b0.y;
        Bs[lc*4+2][lr]      = b0.z;
        Bs[lc*4+3][lr]      = b0.w;
        __syncthreads();

#pragma unroll
        for (int kk = 0; kk < 16; kk++) {
            float4 alo = *(const float4*)&As[kk][tm*8];
            float4 ahi = *(const float4*)&As[kk][tm*8 + 4];
            float4 bb  = *(const float4*)&Bs[kk][tn*4];
            float av[8] = {alo.x, alo.y, alo.z, alo.w, ahi.x, ahi.y, ahi.z, ahi.w};
            float bv[4] = {bb.x, bb.y, bb.z, bb.w};
#pragma unroll
            for (int i = 0; i < 8; i++)
#pragma unroll
                for (int j = 0; j < 4; j++)
                    acc[i][j] = fmaf(av[i], bv[j], acc[i][j]);
        }
        __syncthreads();
    }

    // epilogue: write to [b,h,s,e]; BN=64 == one head, so h = n0/64, e = tn*4..+3
    const int h = n0 >> 6;
#pragma unroll
    for (int i = 0; i < 8; i++) {
        int m = m0 + tm * 8 + i;
        int b = m / SS;
        int s = m % SS;
        float4 v = make_float4(acc[i][0], acc[i][1], acc[i][2], acc[i][3]);
        *(float4*)&out[(((size_t)(b * NH + h)) * SS + s) * EE + tn * 4] = v;
    }
}

// ---------------------------------------------------------------------------
// Flash attention over one (b,h, 64-row q tile).
//   grid: (SS/64, BB*NH), 256 threads, 4x4 microtile on 64x64 tiles.
//   Dynamic smem: Qs_t[64][64] + Ks_t[64][64] + Vs[64][64] + Ps[64][65]
// ---------------------------------------------------------------------------
#define ATTN_SMEM_FLOATS (3*64*64 + 64*65)
#define ATTN_SMEM_BYTES  (ATTN_SMEM_FLOATS * 4)

__global__ __launch_bounds__(256)
void attn_kernel(float* __restrict__ out)
{
    extern __shared__ float sm[];
    float* Qs = sm;                 // [e][i]  stride 64
    float* Ks = sm + 64*64;         // [e][j]  stride 64
    float* Vs = sm + 2*64*64;       // [j][e]  stride 64
    float* Ps = sm + 3*64*64;       // [i][j]  stride 65 (conflict-free PV reads)

    const int bh = blockIdx.y;
    const int q0 = blockIdx.x * 64;
    const float* Q = g_q + (size_t)bh * SS * EE;
    const float* K = g_k + (size_t)bh * SS * EE;
    const float* V = g_v + (size_t)bh * SS * EE;

    const int t  = threadIdx.x;
    const int tm = t >> 4;          // 0..15 -> q rows tm*4
    const int tn = t & 15;          // 0..15 -> cols tn*4

    // load Q tile transposed: 64 rows x 64 e = 1024 float4, 4 per thread
#pragma unroll
    for (int i = 0; i < 4; i++) {
        int f = i * 256 + t;
        int r = f >> 4;             // 0..63
        int c = f & 15;             // 0..15
        float4 v = *(const float4*)&Q[(size_t)(q0 + r) * EE + c * 4];
        Qs[(c*4+0)*64 + r] = v.x;
        Qs[(c*4+1)*64 + r] = v.y;
        Qs[(c*4+2)*64 + r] = v.z;
        Qs[(c*4+3)*64 + r] = v.w;
    }

    float m_r[4], l_r[4], o[4][4];
#pragma unroll
    for (int i = 0; i < 4; i++) {
        m_r[i] = -1e30f;
        l_r[i] = 0.0f;
#pragma unroll
        for (int j = 0; j < 4; j++) o[i][j] = 0.0f;
    }

    for (int kv0 = 0; kv0 < SS; kv0 += 64) {
        __syncthreads();   // protect Ks/Vs/Ps from previous iteration

        // load K (transposed) and V tiles
#pragma unroll
        for (int i = 0; i < 4; i++) {
            int f = i * 256 + t;
            int r = f >> 4;
            int c = f & 15;
            float4 kv = *(const float4*)&K[(size_t)(kv0 + r) * EE + c * 4];
            Ks[(c*4+0)*64 + r] = kv.x;
            Ks[(c*4+1)*64 + r] = kv.y;
            Ks[(c*4+2)*64 + r] = kv.z;
            Ks[(c*4+3)*64 + r] = kv.w;
            float4 vv = *(const float4*)&V[(size_t)(kv0 + r) * EE + c * 4];
            *(float4*)&Vs[r*64 + c*4] = vv;
        }
        __syncthreads();

        // ---- S = Q K^T * 1/sqrt(E) ----
        float s[4][4];
#pragma unroll
        for (int i = 0; i < 4; i++)
#pragma unroll
            for (int j = 0; j < 4; j++) s[i][j] = 0.0f;

#pragma unroll 8
        for (int e = 0; e < 64; e++) {
            float4 q = *(const float4*)&Qs[e*64 + tm*4];
            float4 k = *(const float4*)&Ks[e*64 + tn*4];
            float qv[4] = {q.x, q.y, q.z, q.w};
            float kv[4] = {k.x, k.y, k.z, k.w};
#pragma unroll
            for (int i = 0; i < 4; i++)
#pragma unroll
                for (int j = 0; j < 4; j++)
                    s[i][j] = fmaf(qv[i], kv[j], s[i][j]);
        }

        // ---- online softmax update (rows owned by tm; reduce across 16 tn lanes) ----
#pragma unroll
        for (int i = 0; i < 4; i++) {
            float tmax = s[i][0];
#pragma unroll
            for (int j = 1; j < 4; j++) tmax = fmaxf(tmax, s[i][j]);
            tmax *= 0.125f;
#pragma unroll
            for (int d = 8; d >= 1; d >>= 1)
                tmax = fmaxf(tmax, __shfl_xor_sync(0xffffffffu, tmax, d));

            float m_new = fmaxf(m_r[i], tmax);
            float alpha = __expf(m_r[i] - m_new);

            float rsum = 0.0f;
            float p[4];
#pragma unroll
            for (int j = 0; j < 4; j++) {
                p[j] = __expf(s[i][j] * 0.125f - m_new);
                rsum += p[j];
            }
#pragma unroll
            for (int d = 8; d >= 1; d >>= 1)
                rsum += __shfl_xor_sync(0xffffffffu, rsum, d);

            l_r[i] = l_r[i] * alpha + rsum;
            m_r[i] = m_new;
#pragma unroll
            for (int j = 0; j < 4; j++) {
                o[i][j] *= alpha;
                Ps[(tm*4 + i)*65 + tn*4 + j] = p[j];
            }
        }
        __syncthreads();

        // ---- O += P V ----
#pragma unroll 4
        for (int j = 0; j < 64; j++) {
            float4 v = *(const float4*)&Vs[j*64 + tn*4];
            float p0 = Ps[(tm*4+0)*65 + j];
            float p1 = Ps[(tm*4+1)*65 + j];
            float p2 = Ps[(tm*4+2)*65 + j];
            float p3 = Ps[(tm*4+3)*65 + j];
            o[0][0] = fmaf(p0, v.x, o[0][0]); o[0][1] = fmaf(p0, v.y, o[0][1]);
            o[0][2] = fmaf(p0, v.z, o[0][2]); o[0][3] = fmaf(p0, v.w, o[0][3]);
            o[1][0] = fmaf(p1, v.x, o[1][0]); o[1][1] = fmaf(p1, v.y, o[1][1]);
            o[1][2] = fmaf(p1, v.z, o[1][2]); o[1][3] = fmaf(p1, v.w, o[1][3]);
            o[2][0] = fmaf(p2, v.x, o[2][0]); o[2][1] = fmaf(p2, v.y, o[2][1]);
            o[2][2] = fmaf(p2, v.z, o[2][2]); o[2][3] = fmaf(p2, v.w, o[2][3]);
            o[3][0] = fmaf(p3, v.x, o[3][0]); o[3][1] = fmaf(p3, v.y, o[3][1]);
            o[3][2] = fmaf(p3, v.z, o[3][2]); o[3][3] = fmaf(p3, v.w, o[3][3]);
        }
    }

    // ---- epilogue: out[b][s][h*64+e] = O / l ----
    const int b = bh / NH;
    const int h = bh % NH;
#pragma unroll
    for (int i = 0; i < 4; i++) {
        float inv_l = 1.0f / l_r[i];
        int sidx = q0 + tm*4 + i;
        float4 v = make_float4(o[i][0]*inv_l, o[i][1]*inv_l, o[i][2]*inv_l, o[i][3]*inv_l);
        *(float4*)&out[((size_t)(b * SS + sidx)) * HS + h * EE + tn * 4] = v;
    }
}

// ---------------------------------------------------------------------------
extern "C" void kernel_launch(void* const* d_in, const int* in_sizes, int n_in,
                              void* d_out, int out_size)
{
    const float* x  = (const float*)d_in[0];
    const float* Wq = (const float*)d_in[1];
    const float* Wk = (const float*)d_in[2];
    const float* Wv = (const float*)d_in[3];
    float* out = (float*)d_out;

    cudaFuncSetAttribute(attn_kernel,
                         cudaFuncAttributeMaxDynamicSharedMemorySize,
                         ATTN_SMEM_BYTES);

    dim3 ggrid(BB * SS / 128, HS / 64, 3);
    qkv_gemm<<<ggrid, 256>>>(x, Wq, Wk, Wv);

    dim3 agrid(SS / 64, BB * NH);
    attn_kernel<<<agrid, 256, ATTN_SMEM_BYTES>>>(out);
}